// round 6
// baseline (speedup 1.0000x reference)
#include <cuda_runtime.h>
#include <math.h>
#include <stdint.h>

// Problem constants
#define Bv   4
#define Sv   2048
#define Dv   512
#define Hv   8
#define Ev   4
#define HDv  64
#define Mv   (Bv * Sv)     // 8192
#define DEv  (Dv * Ev)     // 2048
#define QKVN (3 * Dv)      // 1536

// Scratch (device globals; no allocation allowed)
__device__ float g_qkv [Mv * QKVN];    // q|k|v concatenated, row stride 1536
__device__ float g_o   [Mv * Dv];
__device__ float g_x1  [Mv * Dv];
__device__ float g_h   [Mv * DEv];
__device__ float g_xr  [Mv * Dv];      // tf32-rounded x
__device__ float g_wqkv[Dv * QKVN];    // [Wq*s | Wk*s | Wv] rounded
__device__ float g_wor [Dv * Dv];
__device__ float g_w1r [Dv * DEv];
__device__ float g_w2r [DEv * Dv];

enum { EP_NONE = 0, EP_RES = 1, EP_BIAS_GELU = 2, EP_BIAS_RES = 3 };

__device__ __forceinline__ float gelu_tanh(float x) {
    float x3 = x * x * x;
    float t = tanhf(0.7978845608028654f * (x + 0.044715f * x3));
    return 0.5f * x * (1.0f + t);
}

__device__ __forceinline__ uint32_t f2tf32(float x) {
    uint32_t r;
    asm("cvt.rna.tf32.f32 %0, %1;" : "=r"(r) : "f"(x));
    return r;
}
__device__ __forceinline__ float rna(float x) { return __uint_as_float(f2tf32(x)); }

__device__ __forceinline__ uint32_t smem_u32(const void* p) {
    uint32_t a;
    asm("{ .reg .u64 t; cvta.to.shared.u64 t, %1; cvt.u32.u64 %0, t; }"
        : "=r"(a) : "l"(p));
    return a;
}

#define CP_ASYNC16(dst, src) \
    asm volatile("cp.async.cg.shared.global [%0], [%1], 16;" :: "r"(dst), "l"(src))
#define CP_COMMIT() asm volatile("cp.async.commit_group;" ::: "memory")
#define CP_WAIT(n)  asm volatile("cp.async.wait_group %0;" :: "n"(n) : "memory")

__device__ __forceinline__ void mma_tf32(float c[4], uint32_t a0, uint32_t a1,
                                         uint32_t a2, uint32_t a3,
                                         uint32_t b0, uint32_t b1) {
    asm volatile(
        "mma.sync.aligned.m16n8k8.row.col.f32.tf32.tf32.f32 "
        "{%0,%1,%2,%3}, {%4,%5,%6,%7}, {%8,%9}, {%0,%1,%2,%3};"
        : "+f"(c[0]), "+f"(c[1]), "+f"(c[2]), "+f"(c[3])
        : "r"(a0), "r"(a1), "r"(a2), "r"(a3), "r"(b0), "r"(b1));
}

// ---------------------------------------------------------------------------
// Pre-round: weights (scale folded into Wq,Wk) and x to tf32, once per call.
// ---------------------------------------------------------------------------
__global__ __launch_bounds__(256)
void preround(const float* __restrict__ x,  const float* __restrict__ Wq,
              const float* __restrict__ Wk, const float* __restrict__ Wv,
              const float* __restrict__ Wo, const float* __restrict__ W1,
              const float* __restrict__ W2, float scale)
{
    const int i = blockIdx.x * blockDim.x + threadIdx.x;
    const int nt = gridDim.x * blockDim.x;
    for (int idx = i; idx < Dv * QKVN; idx += nt) {
        int d = idx / QKVN, j = idx % QKVN;
        float v = (j < Dv)     ? Wq[d * Dv + j] * scale
                : (j < 2 * Dv) ? Wk[d * Dv + j - Dv] * scale
                               : Wv[d * Dv + j - 2 * Dv];
        g_wqkv[idx] = rna(v);
    }
    for (int idx = i; idx < Dv * Dv;  idx += nt) g_wor[idx] = rna(Wo[idx]);
    for (int idx = i; idx < Dv * DEv; idx += nt) g_w1r[idx] = rna(W1[idx]);
    for (int idx = i; idx < DEv * Dv; idx += nt) g_w2r[idx] = rna(W2[idx]);
    for (int idx = i; idx < Mv * Dv;  idx += nt) g_xr[idx]  = rna(x[idx]);
}

// ---------------------------------------------------------------------------
// 3-stage cp.async mma.sync tf32 GEMM, single barrier per K-slab.
// A: [M,K] fp32(tf32 bits), B: [K,N] fp32(tf32 bits), C: [M,N].
// CTA 128x128, BK=32, 256 threads, warp grid 4(M)x2(N).
// Stage = A 128x36 + B 32x136 floats = 8960 floats.
// ---------------------------------------------------------------------------
#define AS_STRIDE 36
#define BS_STRIDE 136
#define STG_FLOATS (128 * AS_STRIDE + 32 * BS_STRIDE)   // 8960
#define GEMM_SMEM (3 * STG_FLOATS * (int)sizeof(float)) // 107520

template <int EPI, int RND>
__global__ __launch_bounds__(256)
void gemm_mma(const float* __restrict__ A, const float* __restrict__ Bw,
              const float* __restrict__ bias, const float* __restrict__ res,
              float* __restrict__ C, int M, int N, int K)
{
    extern __shared__ float smf[];

    const int tid = threadIdx.x;
    const int wid = tid >> 5;
    const int lid = tid & 31;
    const int gid = lid >> 2;
    const int tq  = lid & 3;
    const int wm  = (wid >> 1) * 32;
    const int wn  = (wid & 1) * 64;
    const int bm  = blockIdx.y * 128;
    const int bn  = blockIdx.x * 128;
    const int NS  = K >> 5;

    auto issue = [&](int s, int buf) {
        float* ab = smf + buf * STG_FLOATS;
        float* bb = ab + 128 * AS_STRIDE;
        const float* Ap = A + (size_t)bm * K + s * 32;
        const float* Bp = Bw + (size_t)(s * 32) * N + bn;
#pragma unroll
        for (int it = 0; it < 4; it++) {
            int idx = it * 256 + tid;
            int r = idx >> 3, c = (idx & 7) * 4;
            CP_ASYNC16(smem_u32(ab + r * AS_STRIDE + c), Ap + (size_t)r * K + c);
        }
#pragma unroll
        for (int it = 0; it < 4; it++) {
            int idx = it * 256 + tid;
            int r = idx >> 5, c = (idx & 31) * 4;
            CP_ASYNC16(smem_u32(bb + r * BS_STRIDE + c), Bp + (size_t)r * N + c);
        }
        CP_COMMIT();
    };

    float acc[2][8][4];
#pragma unroll
    for (int mt = 0; mt < 2; mt++)
#pragma unroll
        for (int nt = 0; nt < 8; nt++)
#pragma unroll
            for (int u = 0; u < 4; u++) acc[mt][nt][u] = 0.0f;

    issue(0, 0);
    issue(1, 1);

    for (int s = 0; s < NS; s++) {
        if (s == NS - 1) { CP_WAIT(0); } else { CP_WAIT(1); }
        __syncthreads();   // stage s visible to all; all warps done with stage s-1
        if (s + 2 < NS) issue(s + 2, (s + 2) % 3);

        const uint32_t* As = (const uint32_t*)(smf + (s % 3) * STG_FLOATS);
        const uint32_t* Bs = As + 128 * AS_STRIDE;
#pragma unroll
        for (int ks = 0; ks < 4; ks++) {
            uint32_t bfr[8][2];
#pragma unroll
            for (int nt = 0; nt < 8; nt++) {
                bfr[nt][0] = Bs[(ks * 8 + tq)     * BS_STRIDE + wn + nt * 8 + gid];
                bfr[nt][1] = Bs[(ks * 8 + tq + 4) * BS_STRIDE + wn + nt * 8 + gid];
            }
#pragma unroll
            for (int mt = 0; mt < 2; mt++) {
                const int r0 = wm + mt * 16 + gid;
                uint32_t a0 = As[r0       * AS_STRIDE + ks * 8 + tq];
                uint32_t a1 = As[(r0 + 8) * AS_STRIDE + ks * 8 + tq];
                uint32_t a2 = As[r0       * AS_STRIDE + ks * 8 + tq + 4];
                uint32_t a3 = As[(r0 + 8) * AS_STRIDE + ks * 8 + tq + 4];
#pragma unroll
                for (int nt = 0; nt < 8; nt++)
                    mma_tf32(acc[mt][nt], a0, a1, a2, a3, bfr[nt][0], bfr[nt][1]);
            }
        }
    }

    // Epilogue
#pragma unroll
    for (int mt = 0; mt < 2; mt++) {
#pragma unroll
        for (int half = 0; half < 2; half++) {
            const int row = bm + wm + mt * 16 + gid + half * 8;
            float* Crow = C + (size_t)row * N;
            const float* rrow = (EPI == EP_RES || EPI == EP_BIAS_RES)
                                    ? (res + (size_t)row * N) : nullptr;
#pragma unroll
            for (int nt = 0; nt < 8; nt++) {
                const int col = bn + wn + nt * 8 + 2 * tq;
                float v0 = acc[mt][nt][half * 2 + 0];
                float v1 = acc[mt][nt][half * 2 + 1];
                if (EPI == EP_BIAS_GELU || EPI == EP_BIAS_RES) {
                    v0 += bias[col]; v1 += bias[col + 1];
                }
                if (EPI == EP_BIAS_GELU) { v0 = gelu_tanh(v0); v1 = gelu_tanh(v1); }
                if (EPI == EP_RES || EPI == EP_BIAS_RES) {
                    v0 += rrow[col]; v1 += rrow[col + 1];
                }
                if (RND) { v0 = rna(v0); v1 = rna(v1); }
                *(float2*)(Crow + col) = make_float2(v0, v1);
            }
        }
    }
}

// ---------------------------------------------------------------------------
// Flash attention, mma.sync tf32, cp.async 2-stage K/V, single barrier/tile.
// q/k/v are column slices of g_qkv (row stride QKVN).
// SMEM (floats): K0[4096] K1[4096] V0[4608] V1[4608] Ps[8704]; Qstage
// overlaps [V1|Ps] (9216 floats at offset 12800). Total 26112 floats.
// K stored swizzled-natural: chunk' = (ch&8) | ((ch^key)&7). V stride 72.
// ---------------------------------------------------------------------------
#define ATTN_SMEM (26112 * (int)sizeof(float))
#define PS_STRIDE 68

__global__ __launch_bounds__(256)
void attn_mma(const float* __restrict__ qkv, float* __restrict__ o)
{
    extern __shared__ float sm[];
    float* Ps = sm + 17408;

    const int tid = threadIdx.x;
    const int wid = tid >> 5;
    const int lid = tid & 31;
    const int gid = lid >> 2;
    const int tq  = lid & 3;
    const int qt  = blockIdx.x;
    const int h   = blockIdx.y;
    const int b   = blockIdx.z;

    const float* qb = qkv + ((size_t)b * Sv + qt * 128) * QKVN + h * HDv;
    const float* kb = qkv + (size_t)b * Sv * QKVN + Dv + h * HDv;
    const float* vb = qkv + (size_t)b * Sv * QKVN + 2 * Dv + h * HDv;

    auto issue_tile = [&](int kt, int buf) {
#pragma unroll
        for (int it = 0; it < 4; it++) {       // K: swizzled
            int idx = it * 256 + tid;
            int key = idx >> 4, ch = idx & 15;
            int chp = (ch & 8) | ((ch ^ key) & 7);
            CP_ASYNC16(smem_u32(sm + buf * 4096 + key * 64 + chp * 4),
                       kb + (size_t)(kt * 64 + key) * QKVN + ch * 4);
        }
#pragma unroll
        for (int it = 0; it < 4; it++) {       // V: natural, stride 72
            int idx = it * 256 + tid;
            int key = idx >> 4, ch = idx & 15;
            CP_ASYNC16(smem_u32(sm + 8192 + buf * 4608 + key * 72 + ch * 4),
                       vb + (size_t)(kt * 64 + key) * QKVN + ch * 4);
        }
        CP_COMMIT();
    };

    // Kick off tile 0 (K0/V0 disjoint from Qstage region), then stage Q.
    issue_tile(0, 0);

    float* Qs = sm + 12800;   // 128 x 72
#pragma unroll
    for (int it = 0; it < 8; it++) {
        int idx = it * 256 + tid;
        int r = idx >> 4;
        int c = (idx & 15) * 4;
        float4 vq = *(const float4*)(qb + (size_t)r * QKVN + c);
        float* dst = &Qs[r * 72 + c];
        dst[0] = vq.x; dst[1] = vq.y; dst[2] = vq.z; dst[3] = vq.w;
    }
    __syncthreads();

    uint32_t qf[8][4];
    {
        const int r0 = wid * 16 + gid;
#pragma unroll
        for (int ks = 0; ks < 8; ks++) {
            qf[ks][0] = __float_as_uint(Qs[r0       * 72 + ks * 8 + tq]);
            qf[ks][1] = __float_as_uint(Qs[(r0 + 8) * 72 + ks * 8 + tq]);
            qf[ks][2] = __float_as_uint(Qs[r0       * 72 + ks * 8 + tq + 4]);
            qf[ks][3] = __float_as_uint(Qs[(r0 + 8) * 72 + ks * 8 + tq + 4]);
        }
    }
    __syncthreads();   // Qstage region free before issue(1) targets V1

    float oacc[8][4];
#pragma unroll
    for (int dt = 0; dt < 8; dt++)
#pragma unroll
        for (int u = 0; u < 4; u++) oacc[dt][u] = 0.0f;
    float mrow0 = -1e30f, mrow1 = -1e30f, lrow0 = 0.0f, lrow1 = 0.0f;
    float* Pw = Ps + wid * 16 * PS_STRIDE;

    for (int kt = 0; kt < Sv / 64; kt++) {
        const int buf = kt & 1;
        CP_WAIT(0);
        __syncthreads();   // tile kt visible; all warps done with tile kt-1
        if (kt + 1 < Sv / 64) issue_tile(kt + 1, 1 - buf);

        const float* Kb = sm + buf * 4096;
        const float* Vb = sm + 8192 + buf * 4608;

        // ---- S = Q @ K^T ----
        float sacc[8][4];
#pragma unroll
        for (int nt = 0; nt < 8; nt++)
#pragma unroll
            for (int u = 0; u < 4; u++) sacc[nt][u] = 0.0f;
#pragma unroll
        for (int ks = 0; ks < 8; ks++) {
            const int c0 = 2 * ks, c1 = 2 * ks + 1;
            const int ch0 = (c0 & 8) | ((c0 ^ gid) & 7);
            const int ch1 = (c1 & 8) | ((c1 ^ gid) & 7);
#pragma unroll
            for (int nt = 0; nt < 8; nt++) {
                const int koff = (nt * 8 + gid) * 64;
                uint32_t b0 = __float_as_uint(Kb[koff + ch0 * 4 + tq]);
                uint32_t b1 = __float_as_uint(Kb[koff + ch1 * 4 + tq]);
                mma_tf32(sacc[nt], qf[ks][0], qf[ks][1], qf[ks][2], qf[ks][3], b0, b1);
            }
        }

        // ---- online softmax ----
        float mx0 = -1e30f, mx1 = -1e30f;
#pragma unroll
        for (int nt = 0; nt < 8; nt++) {
            mx0 = fmaxf(mx0, fmaxf(sacc[nt][0], sacc[nt][1]));
            mx1 = fmaxf(mx1, fmaxf(sacc[nt][2], sacc[nt][3]));
        }
        mx0 = fmaxf(mx0, __shfl_xor_sync(0xffffffffu, mx0, 1));
        mx0 = fmaxf(mx0, __shfl_xor_sync(0xffffffffu, mx0, 2));
        mx1 = fmaxf(mx1, __shfl_xor_sync(0xffffffffu, mx1, 1));
        mx1 = fmaxf(mx1, __shfl_xor_sync(0xffffffffu, mx1, 2));
        float mn0 = fmaxf(mrow0, mx0), mn1 = fmaxf(mrow1, mx1);
        float corr0 = __expf(mrow0 - mn0), corr1 = __expf(mrow1 - mn1);
        float ps0 = 0.0f, ps1 = 0.0f;
#pragma unroll
        for (int nt = 0; nt < 8; nt++) {
            sacc[nt][0] = __expf(sacc[nt][0] - mn0);
            sacc[nt][1] = __expf(sacc[nt][1] - mn0);
            sacc[nt][2] = __expf(sacc[nt][2] - mn1);
            sacc[nt][3] = __expf(sacc[nt][3] - mn1);
            ps0 += sacc[nt][0] + sacc[nt][1];
            ps1 += sacc[nt][2] + sacc[nt][3];
        }
        ps0 += __shfl_xor_sync(0xffffffffu, ps0, 1);
        ps0 += __shfl_xor_sync(0xffffffffu, ps0, 2);
        ps1 += __shfl_xor_sync(0xffffffffu, ps1, 1);
        ps1 += __shfl_xor_sync(0xffffffffu, ps1, 2);
        lrow0 = lrow0 * corr0 + ps0;
        lrow1 = lrow1 * corr1 + ps1;
        mrow0 = mn0; mrow1 = mn1;
#pragma unroll
        for (int dt = 0; dt < 8; dt++) {
            oacc[dt][0] *= corr0; oacc[dt][1] *= corr0;
            oacc[dt][2] *= corr1; oacc[dt][3] *= corr1;
        }

        // ---- P -> per-warp SMEM -> A-fragments ----
#pragma unroll
        for (int nt = 0; nt < 8; nt++) {
            *(float2*)&Pw[gid       * PS_STRIDE + nt * 8 + 2 * tq] =
                make_float2(sacc[nt][0], sacc[nt][1]);
            *(float2*)&Pw[(gid + 8) * PS_STRIDE + nt * 8 + 2 * tq] =
                make_float2(sacc[nt][2], sacc[nt][3]);
        }
        __syncwarp();

        // ---- O += P @ V ----
#pragma unroll
        for (int ks = 0; ks < 8; ks++) {
            uint32_t a0 = __float_as_uint(Pw[gid       * PS_STRIDE + ks * 8 + tq]);
            uint32_t a1 = __float_as_uint(Pw[(gid + 8) * PS_STRIDE + ks * 8 + tq]);
            uint32_t a2 = __float_as_uint(Pw[gid       * PS_STRIDE + ks * 8 + tq + 4]);
            uint32_t a3 = __float_as_uint(Pw[(gid + 8) * PS_STRIDE + ks * 8 + tq + 4]);
#pragma unroll
            for (int dt = 0; dt < 8; dt++) {
                uint32_t b0 = __float_as_uint(Vb[(ks * 8 + tq)     * 72 + dt * 8 + gid]);
                uint32_t b1 = __float_as_uint(Vb[(ks * 8 + tq + 4) * 72 + dt * 8 + gid]);
                mma_tf32(oacc[dt], a0, a1, a2, a3, b0, b1);
            }
        }
        __syncwarp();
    }

    // ---- normalize, round to tf32 (GEMM A operand), write ----
    float inv0 = 1.0f / lrow0, inv1 = 1.0f / lrow1;
    float* ob = o + ((size_t)b * Sv + qt * 128 + wid * 16) * Dv + h * HDv;
#pragma unroll
    for (int dt = 0; dt < 8; dt++) {
        int col = dt * 8 + 2 * tq;
        *(float2*)(ob + (size_t)gid * Dv + col) =
            make_float2(rna(oacc[dt][0] * inv0), rna(oacc[dt][1] * inv0));
        *(float2*)(ob + (size_t)(gid + 8) * Dv + col) =
            make_float2(rna(oacc[dt][2] * inv1), rna(oacc[dt][3] * inv1));
    }
}

// ---------------------------------------------------------------------------
// Launch
// ---------------------------------------------------------------------------
extern "C" void kernel_launch(void* const* d_in, const int* in_sizes, int n_in,
                              void* d_out, int out_size)
{
    const float* x  = (const float*)d_in[0];
    const float* Wq = (const float*)d_in[1];
    const float* Wk = (const float*)d_in[2];
    const float* Wv = (const float*)d_in[3];
    const float* Wo = (const float*)d_in[4];
    const float* W1 = (const float*)d_in[5];
    const float* b1 = (const float*)d_in[6];
    const float* W2 = (const float*)d_in[7];
    const float* b2 = (const float*)d_in[8];
    float* out = (float*)d_out;

    float *qkv, *o, *x1, *hbuf, *xr, *wqkv, *wor, *w1r, *w2r;
    cudaGetSymbolAddress((void**)&qkv,  g_qkv);
    cudaGetSymbolAddress((void**)&o,    g_o);
    cudaGetSymbolAddress((void**)&x1,   g_x1);
    cudaGetSymbolAddress((void**)&hbuf, g_h);
    cudaGetSymbolAddress((void**)&xr,   g_xr);
    cudaGetSymbolAddress((void**)&wqkv, g_wqkv);
    cudaGetSymbolAddress((void**)&wor,  g_wor);
    cudaGetSymbolAddress((void**)&w1r,  g_w1r);
    cudaGetSymbolAddress((void**)&w2r,  g_w2r);

    cudaFuncSetAttribute(gemm_mma<EP_NONE, 1>,      cudaFuncAttributeMaxDynamicSharedMemorySize, GEMM_SMEM);
    cudaFuncSetAttribute(gemm_mma<EP_RES, 1>,       cudaFuncAttributeMaxDynamicSharedMemorySize, GEMM_SMEM);
    cudaFuncSetAttribute(gemm_mma<EP_BIAS_GELU, 1>, cudaFuncAttributeMaxDynamicSharedMemorySize, GEMM_SMEM);
    cudaFuncSetAttribute(gemm_mma<EP_BIAS_RES, 0>,  cudaFuncAttributeMaxDynamicSharedMemorySize, GEMM_SMEM);
    cudaFuncSetAttribute(attn_mma, cudaFuncAttributeMaxDynamicSharedMemorySize, ATTN_SMEM);

    const float scale = 0.21022410381342865f;  // 512^(-0.25)
    dim3 blk(256);

    preround<<<592, blk>>>(x, Wq, Wk, Wv, Wo, W1, W2, scale);

    // qkv = xr @ [Wq*s|Wk*s|Wv]   (M=8192, N=1536, K=512)
    gemm_mma<EP_NONE, 1><<<dim3(QKVN / 128, Mv / 128), blk, GEMM_SMEM>>>(
        xr, wqkv, nullptr, nullptr, qkv, Mv, QKVN, Dv);

    attn_mma<<<dim3(Sv / 128, Hv, Bv), blk, ATTN_SMEM>>>(qkv, o);

    // x1 = o @ Wo + x
    gemm_mma<EP_RES, 1><<<dim3(Dv / 128, Mv / 128), blk, GEMM_SMEM>>>(
        o, wor, nullptr, x, x1, Mv, Dv, Dv);
    // h = gelu(x1 @ W1 + b1)
    gemm_mma<EP_BIAS_GELU, 1><<<dim3(DEv / 128, Mv / 128), blk, GEMM_SMEM>>>(
        x1, w1r, b1, nullptr, hbuf, Mv, DEv, Dv);
    // out = h @ W2 + b2 + x1
    gemm_mma<EP_BIAS_RES, 0><<<dim3(Dv / 128, Mv / 128), blk, GEMM_SMEM>>>(
        hbuf, w2r, b2, x1, out, Mv, Dv, DEv);
}

// round 7
// speedup vs baseline: 1.0814x; 1.0814x over previous
#include <cuda_runtime.h>
#include <math.h>
#include <stdint.h>

// Problem constants
#define Bv   4
#define Sv   2048
#define Dv   512
#define Hv   8
#define Ev   4
#define HDv  64
#define Mv   (Bv * Sv)     // 8192
#define DEv  (Dv * Ev)     // 2048
#define QKVN (3 * Dv)      // 1536

// Scratch (device globals; no allocation allowed)
__device__ float g_qkv [Mv * QKVN];    // q|k|v concatenated, row stride 1536
__device__ float g_o   [Mv * Dv];
__device__ float g_x1  [Mv * Dv];
__device__ float g_h   [Mv * DEv];
__device__ float g_xr  [Mv * Dv];      // tf32-rounded x
__device__ float g_wqkv[Dv * QKVN];    // [Wq*s | Wk*s | Wv] rounded
__device__ float g_wor [Dv * Dv];
__device__ float g_w1r [Dv * DEv];
__device__ float g_w2r [DEv * Dv];

enum { EP_NONE = 0, EP_RES = 1, EP_BIAS_GELU = 2, EP_BIAS_RES = 3 };

__device__ __forceinline__ float gelu_tanh(float x) {
    float x3 = x * x * x;
    float t = tanhf(0.7978845608028654f * (x + 0.044715f * x3));
    return 0.5f * x * (1.0f + t);
}

__device__ __forceinline__ uint32_t f2tf32(float x) {
    uint32_t r;
    asm("cvt.rna.tf32.f32 %0, %1;" : "=r"(r) : "f"(x));
    return r;
}
__device__ __forceinline__ float rna(float x) { return __uint_as_float(f2tf32(x)); }

__device__ __forceinline__ uint32_t smem_u32(const void* p) {
    uint32_t a;
    asm("{ .reg .u64 t; cvta.to.shared.u64 t, %1; cvt.u32.u64 %0, t; }"
        : "=r"(a) : "l"(p));
    return a;
}

#define CP_ASYNC16(dst, src) \
    asm volatile("cp.async.cg.shared.global [%0], [%1], 16;" :: "r"(dst), "l"(src))
#define CP_COMMIT() asm volatile("cp.async.commit_group;" ::: "memory")
#define CP_WAIT(n)  asm volatile("cp.async.wait_group %0;" :: "n"(n) : "memory")

__device__ __forceinline__ void mma_tf32(float c[4], uint32_t a0, uint32_t a1,
                                         uint32_t a2, uint32_t a3,
                                         uint32_t b0, uint32_t b1) {
    asm volatile(
        "mma.sync.aligned.m16n8k8.row.col.f32.tf32.tf32.f32 "
        "{%0,%1,%2,%3}, {%4,%5,%6,%7}, {%8,%9}, {%0,%1,%2,%3};"
        : "+f"(c[0]), "+f"(c[1]), "+f"(c[2]), "+f"(c[3])
        : "r"(a0), "r"(a1), "r"(a2), "r"(a3), "r"(b0), "r"(b1));
}

// ---------------------------------------------------------------------------
// Pre-round: weights (scale folded into Wq,Wk) and x to tf32, once per call.
// ---------------------------------------------------------------------------
__global__ __launch_bounds__(256)
void preround(const float* __restrict__ x,  const float* __restrict__ Wq,
              const float* __restrict__ Wk, const float* __restrict__ Wv,
              const float* __restrict__ Wo, const float* __restrict__ W1,
              const float* __restrict__ W2, float scale)
{
    const int i = blockIdx.x * blockDim.x + threadIdx.x;
    const int nt = gridDim.x * blockDim.x;
    for (int idx = i; idx < Dv * QKVN; idx += nt) {
        int d = idx / QKVN, j = idx % QKVN;
        float v = (j < Dv)     ? Wq[d * Dv + j] * scale
                : (j < 2 * Dv) ? Wk[d * Dv + j - Dv] * scale
                               : Wv[d * Dv + j - 2 * Dv];
        g_wqkv[idx] = rna(v);
    }
    for (int idx = i; idx < Dv * Dv;  idx += nt) g_wor[idx] = rna(Wo[idx]);
    for (int idx = i; idx < Dv * DEv; idx += nt) g_w1r[idx] = rna(W1[idx]);
    for (int idx = i; idx < DEv * Dv; idx += nt) g_w2r[idx] = rna(W2[idx]);
    for (int idx = i; idx < Mv * Dv;  idx += nt) g_xr[idx]  = rna(x[idx]);
}

// ---------------------------------------------------------------------------
// 3-stage cp.async mma.sync tf32 GEMM, single barrier per K-slab.
// CTA 128x128, BK=32, 256 threads, warp grid 4(M)x2(N).
// __launch_bounds__(256, 2): cap at 128 regs so 2 CTAs co-reside per SM.
// ---------------------------------------------------------------------------
#define AS_STRIDE 36
#define BS_STRIDE 136
#define STG_FLOATS (128 * AS_STRIDE + 32 * BS_STRIDE)   // 8960
#define GEMM_SMEM (3 * STG_FLOATS * (int)sizeof(float)) // 107520

template <int EPI, int RND>
__global__ __launch_bounds__(256, 2)
void gemm_mma(const float* __restrict__ A, const float* __restrict__ Bw,
              const float* __restrict__ bias, const float* __restrict__ res,
              float* __restrict__ C, int M, int N, int K)
{
    extern __shared__ float smf[];

    const int tid = threadIdx.x;
    const int wid = tid >> 5;
    const int lid = tid & 31;
    const int gid = lid >> 2;
    const int tq  = lid & 3;
    const int wm  = (wid >> 1) * 32;
    const int wn  = (wid & 1) * 64;
    const int bm  = blockIdx.y * 128;
    const int bn  = blockIdx.x * 128;
    const int NS  = K >> 5;

    auto issue = [&](int s, int buf) {
        float* ab = smf + buf * STG_FLOATS;
        float* bb = ab + 128 * AS_STRIDE;
        const float* Ap = A + (size_t)bm * K + s * 32;
        const float* Bp = Bw + (size_t)(s * 32) * N + bn;
#pragma unroll
        for (int it = 0; it < 4; it++) {
            int idx = it * 256 + tid;
            int r = idx >> 3, c = (idx & 7) * 4;
            CP_ASYNC16(smem_u32(ab + r * AS_STRIDE + c), Ap + (size_t)r * K + c);
        }
#pragma unroll
        for (int it = 0; it < 4; it++) {
            int idx = it * 256 + tid;
            int r = idx >> 5, c = (idx & 31) * 4;
            CP_ASYNC16(smem_u32(bb + r * BS_STRIDE + c), Bp + (size_t)r * N + c);
        }
        CP_COMMIT();
    };

    float acc[2][8][4];
#pragma unroll
    for (int mt = 0; mt < 2; mt++)
#pragma unroll
        for (int nt = 0; nt < 8; nt++)
#pragma unroll
            for (int u = 0; u < 4; u++) acc[mt][nt][u] = 0.0f;

    issue(0, 0);
    issue(1, 1);

    for (int s = 0; s < NS; s++) {
        if (s == NS - 1) { CP_WAIT(0); } else { CP_WAIT(1); }
        __syncthreads();
        if (s + 2 < NS) issue(s + 2, (s + 2) % 3);

        const uint32_t* As = (const uint32_t*)(smf + (s % 3) * STG_FLOATS);
        const uint32_t* Bs = As + 128 * AS_STRIDE;
#pragma unroll
        for (int ks = 0; ks < 4; ks++) {
            uint32_t bfr[8][2];
#pragma unroll
            for (int nt = 0; nt < 8; nt++) {
                bfr[nt][0] = Bs[(ks * 8 + tq)     * BS_STRIDE + wn + nt * 8 + gid];
                bfr[nt][1] = Bs[(ks * 8 + tq + 4) * BS_STRIDE + wn + nt * 8 + gid];
            }
#pragma unroll
            for (int mt = 0; mt < 2; mt++) {
                const int r0 = wm + mt * 16 + gid;
                uint32_t a0 = As[r0       * AS_STRIDE + ks * 8 + tq];
                uint32_t a1 = As[(r0 + 8) * AS_STRIDE + ks * 8 + tq];
                uint32_t a2 = As[r0       * AS_STRIDE + ks * 8 + tq + 4];
                uint32_t a3 = As[(r0 + 8) * AS_STRIDE + ks * 8 + tq + 4];
#pragma unroll
                for (int nt = 0; nt < 8; nt++)
                    mma_tf32(acc[mt][nt], a0, a1, a2, a3, bfr[nt][0], bfr[nt][1]);
            }
        }
    }

    // Epilogue
#pragma unroll
    for (int mt = 0; mt < 2; mt++) {
#pragma unroll
        for (int half = 0; half < 2; half++) {
            const int row = bm + wm + mt * 16 + gid + half * 8;
            float* Crow = C + (size_t)row * N;
            const float* rrow = (EPI == EP_RES || EPI == EP_BIAS_RES)
                                    ? (res + (size_t)row * N) : nullptr;
#pragma unroll
            for (int nt = 0; nt < 8; nt++) {
                const int col = bn + wn + nt * 8 + 2 * tq;
                float v0 = acc[mt][nt][half * 2 + 0];
                float v1 = acc[mt][nt][half * 2 + 1];
                if (EPI == EP_BIAS_GELU || EPI == EP_BIAS_RES) {
                    v0 += bias[col]; v1 += bias[col + 1];
                }
                if (EPI == EP_BIAS_GELU) { v0 = gelu_tanh(v0); v1 = gelu_tanh(v1); }
                if (EPI == EP_RES || EPI == EP_BIAS_RES) {
                    v0 += rrow[col]; v1 += rrow[col + 1];
                }
                if (RND) { v0 = rna(v0); v1 = rna(v1); }
                *(float2*)(Crow + col) = make_float2(v0, v1);
            }
        }
    }
}

// ---------------------------------------------------------------------------
// Flash attention, mma.sync tf32, cp.async 2-stage K/V (unchanged round 6)
// ---------------------------------------------------------------------------
#define ATTN_SMEM (26112 * (int)sizeof(float))
#define PS_STRIDE 68

__global__ __launch_bounds__(256, 2)
void attn_mma(const float* __restrict__ qkv, float* __restrict__ o)
{
    extern __shared__ float sm[];
    float* Ps = sm + 17408;

    const int tid = threadIdx.x;
    const int wid = tid >> 5;
    const int lid = tid & 31;
    const int gid = lid >> 2;
    const int tq  = lid & 3;
    const int qt  = blockIdx.x;
    const int h   = blockIdx.y;
    const int b   = blockIdx.z;

    const float* qb = qkv + ((size_t)b * Sv + qt * 128) * QKVN + h * HDv;
    const float* kb = qkv + (size_t)b * Sv * QKVN + Dv + h * HDv;
    const float* vb = qkv + (size_t)b * Sv * QKVN + 2 * Dv + h * HDv;

    auto issue_tile = [&](int kt, int buf) {
#pragma unroll
        for (int it = 0; it < 4; it++) {       // K: swizzled
            int idx = it * 256 + tid;
            int key = idx >> 4, ch = idx & 15;
            int chp = (ch & 8) | ((ch ^ key) & 7);
            CP_ASYNC16(smem_u32(sm + buf * 4096 + key * 64 + chp * 4),
                       kb + (size_t)(kt * 64 + key) * QKVN + ch * 4);
        }
#pragma unroll
        for (int it = 0; it < 4; it++) {       // V: natural, stride 72
            int idx = it * 256 + tid;
            int key = idx >> 4, ch = idx & 15;
            CP_ASYNC16(smem_u32(sm + 8192 + buf * 4608 + key * 72 + ch * 4),
                       vb + (size_t)(kt * 64 + key) * QKVN + ch * 4);
        }
        CP_COMMIT();
    };

    issue_tile(0, 0);

    float* Qs = sm + 12800;   // 128 x 72
#pragma unroll
    for (int it = 0; it < 8; it++) {
        int idx = it * 256 + tid;
        int r = idx >> 4;
        int c = (idx & 15) * 4;
        float4 vq = *(const float4*)(qb + (size_t)r * QKVN + c);
        float* dst = &Qs[r * 72 + c];
        dst[0] = vq.x; dst[1] = vq.y; dst[2] = vq.z; dst[3] = vq.w;
    }
    __syncthreads();

    uint32_t qf[8][4];
    {
        const int r0 = wid * 16 + gid;
#pragma unroll
        for (int ks = 0; ks < 8; ks++) {
            qf[ks][0] = __float_as_uint(Qs[r0       * 72 + ks * 8 + tq]);
            qf[ks][1] = __float_as_uint(Qs[(r0 + 8) * 72 + ks * 8 + tq]);
            qf[ks][2] = __float_as_uint(Qs[r0       * 72 + ks * 8 + tq + 4]);
            qf[ks][3] = __float_as_uint(Qs[(r0 + 8) * 72 + ks * 8 + tq + 4]);
        }
    }
    __syncthreads();   // Qstage region free before issue(1) targets V1

    float oacc[8][4];
#pragma unroll
    for (int dt = 0; dt < 8; dt++)
#pragma unroll
        for (int u = 0; u < 4; u++) oacc[dt][u] = 0.0f;
    float mrow0 = -1e30f, mrow1 = -1e30f, lrow0 = 0.0f, lrow1 = 0.0f;
    float* Pw = Ps + wid * 16 * PS_STRIDE;

    for (int kt = 0; kt < Sv / 64; kt++) {
        const int buf = kt & 1;
        CP_WAIT(0);
        __syncthreads();
        if (kt + 1 < Sv / 64) issue_tile(kt + 1, 1 - buf);

        const float* Kb = sm + buf * 4096;
        const float* Vb = sm + 8192 + buf * 4608;

        // ---- S = Q @ K^T ----
        float sacc[8][4];
#pragma unroll
        for (int nt = 0; nt < 8; nt++)
#pragma unroll
            for (int u = 0; u < 4; u++) sacc[nt][u] = 0.0f;
#pragma unroll
        for (int ks = 0; ks < 8; ks++) {
            const int c0 = 2 * ks, c1 = 2 * ks + 1;
            const int ch0 = (c0 & 8) | ((c0 ^ gid) & 7);
            const int ch1 = (c1 & 8) | ((c1 ^ gid) & 7);
#pragma unroll
            for (int nt = 0; nt < 8; nt++) {
                const int koff = (nt * 8 + gid) * 64;
                uint32_t b0 = __float_as_uint(Kb[koff + ch0 * 4 + tq]);
                uint32_t b1 = __float_as_uint(Kb[koff + ch1 * 4 + tq]);
                mma_tf32(sacc[nt], qf[ks][0], qf[ks][1], qf[ks][2], qf[ks][3], b0, b1);
            }
        }

        // ---- online softmax ----
        float mx0 = -1e30f, mx1 = -1e30f;
#pragma unroll
        for (int nt = 0; nt < 8; nt++) {
            mx0 = fmaxf(mx0, fmaxf(sacc[nt][0], sacc[nt][1]));
            mx1 = fmaxf(mx1, fmaxf(sacc[nt][2], sacc[nt][3]));
        }
        mx0 = fmaxf(mx0, __shfl_xor_sync(0xffffffffu, mx0, 1));
        mx0 = fmaxf(mx0, __shfl_xor_sync(0xffffffffu, mx0, 2));
        mx1 = fmaxf(mx1, __shfl_xor_sync(0xffffffffu, mx1, 1));
        mx1 = fmaxf(mx1, __shfl_xor_sync(0xffffffffu, mx1, 2));
        float mn0 = fmaxf(mrow0, mx0), mn1 = fmaxf(mrow1, mx1);
        float corr0 = __expf(mrow0 - mn0), corr1 = __expf(mrow1 - mn1);
        float ps0 = 0.0f, ps1 = 0.0f;
#pragma unroll
        for (int nt = 0; nt < 8; nt++) {
            sacc[nt][0] = __expf(sacc[nt][0] - mn0);
            sacc[nt][1] = __expf(sacc[nt][1] - mn0);
            sacc[nt][2] = __expf(sacc[nt][2] - mn1);
            sacc[nt][3] = __expf(sacc[nt][3] - mn1);
            ps0 += sacc[nt][0] + sacc[nt][1];
            ps1 += sacc[nt][2] + sacc[nt][3];
        }
        ps0 += __shfl_xor_sync(0xffffffffu, ps0, 1);
        ps0 += __shfl_xor_sync(0xffffffffu, ps0, 2);
        ps1 += __shfl_xor_sync(0xffffffffu, ps1, 1);
        ps1 += __shfl_xor_sync(0xffffffffu, ps1, 2);
        lrow0 = lrow0 * corr0 + ps0;
        lrow1 = lrow1 * corr1 + ps1;
        mrow0 = mn0; mrow1 = mn1;
#pragma unroll
        for (int dt = 0; dt < 8; dt++) {
            oacc[dt][0] *= corr0; oacc[dt][1] *= corr0;
            oacc[dt][2] *= corr1; oacc[dt][3] *= corr1;
        }

        // ---- P -> per-warp SMEM -> A-fragments ----
#pragma unroll
        for (int nt = 0; nt < 8; nt++) {
            *(float2*)&Pw[gid       * PS_STRIDE + nt * 8 + 2 * tq] =
                make_float2(sacc[nt][0], sacc[nt][1]);
            *(float2*)&Pw[(gid + 8) * PS_STRIDE + nt * 8 + 2 * tq] =
                make_float2(sacc[nt][2], sacc[nt][3]);
        }
        __syncwarp();

        // ---- O += P @ V ----
#pragma unroll
        for (int ks = 0; ks < 8; ks++) {
            uint32_t a0 = __float_as_uint(Pw[gid       * PS_STRIDE + ks * 8 + tq]);
            uint32_t a1 = __float_as_uint(Pw[(gid + 8) * PS_STRIDE + ks * 8 + tq]);
            uint32_t a2 = __float_as_uint(Pw[gid       * PS_STRIDE + ks * 8 + tq + 4]);
            uint32_t a3 = __float_as_uint(Pw[(gid + 8) * PS_STRIDE + ks * 8 + tq + 4]);
#pragma unroll
            for (int dt = 0; dt < 8; dt++) {
                uint32_t b0 = __float_as_uint(Vb[(ks * 8 + tq)     * 72 + dt * 8 + gid]);
                uint32_t b1 = __float_as_uint(Vb[(ks * 8 + tq + 4) * 72 + dt * 8 + gid]);
                mma_tf32(oacc[dt], a0, a1, a2, a3, b0, b1);
            }
        }
        __syncwarp();
    }

    // ---- normalize, round to tf32 (GEMM A operand), write ----
    float inv0 = 1.0f / lrow0, inv1 = 1.0f / lrow1;
    float* ob = o + ((size_t)b * Sv + qt * 128 + wid * 16) * Dv + h * HDv;
#pragma unroll
    for (int dt = 0; dt < 8; dt++) {
        int col = dt * 8 + 2 * tq;
        *(float2*)(ob + (size_t)gid * Dv + col) =
            make_float2(rna(oacc[dt][0] * inv0), rna(oacc[dt][1] * inv0));
        *(float2*)(ob + (size_t)(gid + 8) * Dv + col) =
            make_float2(rna(oacc[dt][2] * inv1), rna(oacc[dt][3] * inv1));
    }
}

// ---------------------------------------------------------------------------
// Launch
// ---------------------------------------------------------------------------
extern "C" void kernel_launch(void* const* d_in, const int* in_sizes, int n_in,
                              void* d_out, int out_size)
{
    const float* x  = (const float*)d_in[0];
    const float* Wq = (const float*)d_in[1];
    const float* Wk = (const float*)d_in[2];
    const float* Wv = (const float*)d_in[3];
    const float* Wo = (const float*)d_in[4];
    const float* W1 = (const float*)d_in[5];
    const float* b1 = (const float*)d_in[6];
    const float* W2 = (const float*)d_in[7];
    const float* b2 = (const float*)d_in[8];
    float* out = (float*)d_out;

    float *qkv, *o, *x1, *hbuf, *xr, *wqkv, *wor, *w1r, *w2r;
    cudaGetSymbolAddress((void**)&qkv,  g_qkv);
    cudaGetSymbolAddress((void**)&o,    g_o);
    cudaGetSymbolAddress((void**)&x1,   g_x1);
    cudaGetSymbolAddress((void**)&hbuf, g_h);
    cudaGetSymbolAddress((void**)&xr,   g_xr);
    cudaGetSymbolAddress((void**)&wqkv, g_wqkv);
    cudaGetSymbolAddress((void**)&wor,  g_wor);
    cudaGetSymbolAddress((void**)&w1r,  g_w1r);
    cudaGetSymbolAddress((void**)&w2r,  g_w2r);

    cudaFuncSetAttribute(gemm_mma<EP_NONE, 1>,      cudaFuncAttributeMaxDynamicSharedMemorySize, GEMM_SMEM);
    cudaFuncSetAttribute(gemm_mma<EP_RES, 1>,       cudaFuncAttributeMaxDynamicSharedMemorySize, GEMM_SMEM);
    cudaFuncSetAttribute(gemm_mma<EP_BIAS_GELU, 1>, cudaFuncAttributeMaxDynamicSharedMemorySize, GEMM_SMEM);
    cudaFuncSetAttribute(gemm_mma<EP_BIAS_RES, 0>,  cudaFuncAttributeMaxDynamicSharedMemorySize, GEMM_SMEM);
    cudaFuncSetAttribute(attn_mma, cudaFuncAttributeMaxDynamicSharedMemorySize, ATTN_SMEM);

    const float scale = 0.21022410381342865f;  // 512^(-0.25)
    dim3 blk(256);

    preround<<<592, blk>>>(x, Wq, Wk, Wv, Wo, W1, W2, scale);

    // qkv = xr @ [Wq*s|Wk*s|Wv]   (M=8192, N=1536, K=512)
    gemm_mma<EP_NONE, 1><<<dim3(QKVN / 128, Mv / 128), blk, GEMM_SMEM>>>(
        xr, wqkv, nullptr, nullptr, qkv, Mv, QKVN, Dv);

    attn_mma<<<dim3(Sv / 128, Hv, Bv), blk, ATTN_SMEM>>>(qkv, o);

    // x1 = o @ Wo + x
    gemm_mma<EP_RES, 1><<<dim3(Dv / 128, Mv / 128), blk, GEMM_SMEM>>>(
        o, wor, nullptr, x, x1, Mv, Dv, Dv);
    // h = gelu(x1 @ W1 + b1)
    gemm_mma<EP_BIAS_GELU, 1><<<dim3(DEv / 128, Mv / 128), blk, GEMM_SMEM>>>(
        x1, w1r, b1, nullptr, hbuf, Mv, DEv, Dv);
    // out = h @ W2 + b2 + x1
    gemm_mma<EP_BIAS_RES, 0><<<dim3(Dv / 128, Mv / 128), blk, GEMM_SMEM>>>(
        hbuf, w2r, b2, x1, out, Mv, Dv, DEv);
}

// round 8
// speedup vs baseline: 1.1541x; 1.0672x over previous
#include <cuda_runtime.h>
#include <math.h>
#include <stdint.h>

// Problem constants
#define Bv   4
#define Sv   2048
#define Dv   512
#define Hv   8
#define Ev   4
#define HDv  64
#define Mv   (Bv * Sv)     // 8192
#define DEv  (Dv * Ev)     // 2048
#define QKVN (3 * Dv)      // 1536

// Scratch (device globals; no allocation allowed)
__device__ float g_qk  [Mv * 1024];     // q|k, row stride 1024
__device__ float g_vt  [Dv * Mv];       // v transposed: [(h*64+d)][b*2048+s]
__device__ float g_o   [Mv * Dv];
__device__ float g_x1  [Mv * Dv];
__device__ float g_h   [Mv * DEv];
__device__ float g_xr  [Mv * Dv];       // tf32-rounded x
__device__ float g_wqkvT[QKVN * Dv];    // [Wq*s|Wk*s|Wv]^T rounded: [N][K]
__device__ float g_woT [Dv * Dv];
__device__ float g_w1T [DEv * Dv];
__device__ float g_w2T [Dv * DEv];

enum { EP_QKV = 0, EP_RES = 1, EP_BIAS_GELU = 2, EP_BIAS_RES = 3 };

__device__ __forceinline__ float gelu_tanh(float x) {
    float x3 = x * x * x;
    float t = tanhf(0.7978845608028654f * (x + 0.044715f * x3));
    return 0.5f * x * (1.0f + t);
}

__device__ __forceinline__ uint32_t f2tf32(float x) {
    uint32_t r;
    asm("cvt.rna.tf32.f32 %0, %1;" : "=r"(r) : "f"(x));
    return r;
}
__device__ __forceinline__ float rna(float x) { return __uint_as_float(f2tf32(x)); }

__device__ __forceinline__ uint32_t smem_u32(const void* p) {
    uint32_t a;
    asm("{ .reg .u64 t; cvta.to.shared.u64 t, %1; cvt.u32.u64 %0, t; }"
        : "=r"(a) : "l"(p));
    return a;
}

#define CP_ASYNC16(dst, src) \
    asm volatile("cp.async.cg.shared.global [%0], [%1], 16;" :: "r"(dst), "l"(src))
#define CP_COMMIT() asm volatile("cp.async.commit_group;" ::: "memory")
#define CP_WAIT(n)  asm volatile("cp.async.wait_group %0;" :: "n"(n) : "memory")

#define LDSM_X4(r0, r1, r2, r3, a) \
    asm volatile("ldmatrix.sync.aligned.m8n8.x4.shared.b16 {%0,%1,%2,%3}, [%4];" \
        : "=r"(r0), "=r"(r1), "=r"(r2), "=r"(r3) : "r"(a))

__device__ __forceinline__ void mma_tf32(float c[4], uint32_t a0, uint32_t a1,
                                         uint32_t a2, uint32_t a3,
                                         uint32_t b0, uint32_t b1) {
    asm volatile(
        "mma.sync.aligned.m16n8k8.row.col.f32.tf32.tf32.f32 "
        "{%0,%1,%2,%3}, {%4,%5,%6,%7}, {%8,%9}, {%0,%1,%2,%3};"
        : "+f"(c[0]), "+f"(c[1]), "+f"(c[2]), "+f"(c[3])
        : "r"(a0), "r"(a1), "r"(a2), "r"(a3), "r"(b0), "r"(b1));
}

// ---------------------------------------------------------------------------
// Tiled transpose+round: dst[C][R] = rna(src[R][C] * scale)
// ---------------------------------------------------------------------------
__global__ __launch_bounds__(256)
void transpose_rnd(const float* __restrict__ src, float* __restrict__ dst,
                   int R, int C, float scale)
{
    __shared__ float t[32][33];
    const int tx = threadIdx.x, ty = threadIdx.y;
    const int bx = blockIdx.x * 32, by = blockIdx.y * 32;
#pragma unroll
    for (int j = 0; j < 4; j++)
        t[ty + 8 * j][tx] = src[(size_t)(by + ty + 8 * j) * C + bx + tx];
    __syncthreads();
#pragma unroll
    for (int j = 0; j < 4; j++)
        dst[(size_t)(bx + ty + 8 * j) * R + by + tx] = rna(t[tx][ty + 8 * j] * scale);
}

__global__ __launch_bounds__(256)
void round_x(const float* __restrict__ x)
{
    const int i = blockIdx.x * 256 + threadIdx.x;
    const int nt = gridDim.x * 256;
    for (int idx = i; idx < Mv * Dv; idx += nt) g_xr[idx] = rna(x[idx]);
}

// ---------------------------------------------------------------------------
// 3-stage cp.async mma.sync tf32 GEMM with ldmatrix fragment loads.
// A: [M,K] row-major; BT: [N,K] row-major (transposed weights); C: [M,ldc].
// CTA 128x128, BK=32, 256 threads, warp grid 4(M)x2(N).
// Both tiles staged [128][36] (144B rows, ldmatrix conflict-free).
// ---------------------------------------------------------------------------
#define TS 36
#define STG_FLOATS (2 * 128 * TS)                        // 9216
#define GEMM_SMEM (3 * STG_FLOATS * (int)sizeof(float))  // 110592

template <int EPI, int RND>
__global__ __launch_bounds__(256, 2)
void gemm_mma(const float* __restrict__ A, const float* __restrict__ BT,
              const float* __restrict__ bias, const float* __restrict__ res,
              float* __restrict__ C, int M, int N, int K)
{
    extern __shared__ float smf[];

    const int tid = threadIdx.x;
    const int wid = tid >> 5;
    const int lid = tid & 31;
    const int gid = lid >> 2;
    const int tq  = lid & 3;
    const int wm  = (wid >> 1) * 32;
    const int wn  = (wid & 1) * 64;
    const int bm  = blockIdx.y * 128;
    const int bn  = blockIdx.x * 128;
    const int NS  = K >> 5;

    // ldmatrix per-thread address components
    const int lrow  = (lid & 7) + ((lid >> 3) & 1) * 8;  // A-type 16-row tiles
    const int ahalf = lid >> 4;                          // A 16B col half
    const int brow  = lid & 7;                           // B-type 8-row tiles
    const int bhalf = (lid >> 3) & 1;
    const int bsel  = (lid >> 4) & 1;                    // B nt-of-pair

    auto issue = [&](int s, int buf) {
        float* ab = smf + buf * STG_FLOATS;
        float* bb = ab + 128 * TS;
        const float* Ap = A  + (size_t)bm * K + s * 32;
        const float* Bp = BT + (size_t)bn * K + s * 32;
#pragma unroll
        for (int it = 0; it < 4; it++) {
            int idx = it * 256 + tid;
            int r = idx >> 3, c = (idx & 7) * 4;
            CP_ASYNC16(smem_u32(ab + r * TS + c), Ap + (size_t)r * K + c);
        }
#pragma unroll
        for (int it = 0; it < 4; it++) {
            int idx = it * 256 + tid;
            int r = idx >> 3, c = (idx & 7) * 4;
            CP_ASYNC16(smem_u32(bb + r * TS + c), Bp + (size_t)r * K + c);
        }
        CP_COMMIT();
    };

    float acc[2][8][4];
#pragma unroll
    for (int mt = 0; mt < 2; mt++)
#pragma unroll
        for (int nt = 0; nt < 8; nt++)
#pragma unroll
            for (int u = 0; u < 4; u++) acc[mt][nt][u] = 0.0f;

    issue(0, 0);
    issue(1, 1);

    for (int s = 0; s < NS; s++) {
        if (s == NS - 1) { CP_WAIT(0); } else { CP_WAIT(1); }
        __syncthreads();
        if (s + 2 < NS) issue(s + 2, (s + 2) % 3);

        const uint32_t stage = smem_u32(smf + (s % 3) * STG_FLOATS);
        const uint32_t a_base = stage + ((wm + lrow) * TS + ahalf * 4) * 4;
        const uint32_t b_base = stage + 128 * TS * 4
                              + ((wn + bsel * 8 + brow) * TS + bhalf * 4) * 4;
#pragma unroll
        for (int ks = 0; ks < 4; ks++) {
            uint32_t a[2][4];
#pragma unroll
            for (int mt = 0; mt < 2; mt++)
                LDSM_X4(a[mt][0], a[mt][1], a[mt][2], a[mt][3],
                        a_base + mt * (16 * TS * 4) + ks * 32);
#pragma unroll
            for (int p = 0; p < 4; p++) {
                uint32_t b0, b1, b2, b3;
                LDSM_X4(b0, b1, b2, b3, b_base + p * (16 * TS * 4) + ks * 32);
#pragma unroll
                for (int mt = 0; mt < 2; mt++) {
                    mma_tf32(acc[mt][2 * p],     a[mt][0], a[mt][1], a[mt][2], a[mt][3], b0, b1);
                    mma_tf32(acc[mt][2 * p + 1], a[mt][0], a[mt][1], a[mt][2], a[mt][3], b2, b3);
                }
            }
        }
    }

    // Epilogue
    float* vt = (float*)res;   // EP_QKV: res carries vt pointer
#pragma unroll
    for (int mt = 0; mt < 2; mt++) {
#pragma unroll
        for (int half = 0; half < 2; half++) {
            const int row = bm + wm + mt * 16 + gid + half * 8;
#pragma unroll
            for (int nt = 0; nt < 8; nt++) {
                const int col = bn + wn + nt * 8 + 2 * tq;
                float v0 = acc[mt][nt][half * 2 + 0];
                float v1 = acc[mt][nt][half * 2 + 1];
                if (EPI == EP_QKV) {
                    if (bn < 1024) {
                        *(float2*)(C + (size_t)row * 1024 + col) =
                            make_float2(rna(v0), rna(v1));
                    } else {
                        vt[(size_t)(col - 1024) * Mv + row] = rna(v0);
                        vt[(size_t)(col - 1023) * Mv + row] = rna(v1);
                    }
                } else {
                    if (EPI == EP_BIAS_GELU || EPI == EP_BIAS_RES) {
                        v0 += bias[col]; v1 += bias[col + 1];
                    }
                    if (EPI == EP_BIAS_GELU) { v0 = gelu_tanh(v0); v1 = gelu_tanh(v1); }
                    if (EPI == EP_RES || EPI == EP_BIAS_RES) {
                        v0 += res[(size_t)row * N + col];
                        v1 += res[(size_t)row * N + col + 1];
                    }
                    if (RND) { v0 = rna(v0); v1 = rna(v1); }
                    *(float2*)(C + (size_t)row * N + col) = make_float2(v0, v1);
                }
            }
        }
    }
}

// ---------------------------------------------------------------------------
// Flash attention: mma.sync tf32, ldmatrix fragments, cp.async 2-stage.
// K from g_qk cols [512,1024) natural [key][d] (n-major for S=Q@K^T).
// V from g_vt [d][key] (n-major for P@V).
// SMEM floats: K0[4352] K1[4352] V0[4352] V1[4352] Ps[8704]; Qs overlaps Ps.
// All tiles stride 68 (272B rows -> ldmatrix conflict-free).
// ---------------------------------------------------------------------------
#define ATTN_SMEM (26112 * (int)sizeof(float))

__global__ __launch_bounds__(256, 2)
void attn_mma(const float* __restrict__ qk, const float* __restrict__ vt,
              float* __restrict__ o)
{
    extern __shared__ float sm[];
    float* Ps = sm + 17408;
    float* Qs = sm + 17408;   // overlap: Q staged before Ps first used

    const int tid = threadIdx.x;
    const int wid = tid >> 5;
    const int lid = tid & 31;
    const int gid = lid >> 2;
    const int tq  = lid & 3;
    const int qt  = blockIdx.x;
    const int h   = blockIdx.y;
    const int b   = blockIdx.z;

    const int lrow  = (lid & 7) + ((lid >> 3) & 1) * 8;
    const int ahalf = lid >> 4;
    const int brow  = lid & 7;
    const int bhalf = (lid >> 3) & 1;
    const int bsel  = (lid >> 4) & 1;

    const float* qb  = qk + ((size_t)b * Sv + qt * 128) * 1024 + h * HDv;
    const float* kb  = qk + (size_t)b * Sv * 1024 + 512 + h * HDv;
    const float* vtb = vt + (size_t)(h * HDv) * Mv + b * Sv;

    auto issue_tile = [&](int kt, int buf) {
#pragma unroll
        for (int it = 0; it < 4; it++) {       // K: [key][68]
            int idx = it * 256 + tid;
            int key = idx >> 4, ch = idx & 15;
            CP_ASYNC16(smem_u32(sm + buf * 4352 + key * 68 + ch * 4),
                       kb + (size_t)(kt * 64 + key) * 1024 + ch * 4);
        }
#pragma unroll
        for (int it = 0; it < 4; it++) {       // V: [d][68] from vt rows
            int idx = it * 256 + tid;
            int d = idx >> 4, ch = idx & 15;
            CP_ASYNC16(smem_u32(sm + 8704 + buf * 4352 + d * 68 + ch * 4),
                       vtb + (size_t)d * Mv + kt * 64 + ch * 4);
        }
        CP_COMMIT();
    };

    issue_tile(0, 0);

    // Stage Q [128][68]
#pragma unroll
    for (int it = 0; it < 8; it++) {
        int idx = it * 256 + tid;
        int r = idx >> 4;
        int c = (idx & 15) * 4;
        float4 vq = *(const float4*)(qb + (size_t)r * 1024 + c);
        float* dst = &Qs[r * 68 + c];
        dst[0] = vq.x; dst[1] = vq.y; dst[2] = vq.z; dst[3] = vq.w;
    }
    __syncthreads();

    uint32_t qf[8][4];
    {
        const uint32_t qaddr = smem_u32(Qs) + ((wid * 16 + lrow) * 68 + ahalf * 4) * 4;
#pragma unroll
        for (int ks = 0; ks < 8; ks++)
            LDSM_X4(qf[ks][0], qf[ks][1], qf[ks][2], qf[ks][3], qaddr + ks * 32);
    }
    __syncthreads();   // Qs region becomes Ps after this point

    float oacc[8][4];
#pragma unroll
    for (int dt = 0; dt < 8; dt++)
#pragma unroll
        for (int u = 0; u < 4; u++) oacc[dt][u] = 0.0f;
    float mrow0 = -1e30f, mrow1 = -1e30f, lrow0 = 0.0f, lrow1 = 0.0f;
    float* Pw = Ps + wid * 16 * 68;
    const uint32_t paddr = smem_u32(Pw) + (lrow * 68 + ahalf * 4) * 4;

    for (int kt = 0; kt < Sv / 64; kt++) {
        const int buf = kt & 1;
        CP_WAIT(0);
        __syncthreads();
        if (kt + 1 < Sv / 64) issue_tile(kt + 1, 1 - buf);

        const uint32_t kaddr = smem_u32(sm + buf * 4352)
                             + ((bsel * 8 + brow) * 68 + bhalf * 4) * 4;
        const uint32_t vaddr = smem_u32(sm + 8704 + buf * 4352)
                             + ((bsel * 8 + brow) * 68 + bhalf * 4) * 4;

        // ---- S = Q @ K^T ----
        float sacc[8][4];
#pragma unroll
        for (int nt = 0; nt < 8; nt++)
#pragma unroll
            for (int u = 0; u < 4; u++) sacc[nt][u] = 0.0f;
#pragma unroll
        for (int ks = 0; ks < 8; ks++) {
#pragma unroll
            for (int p = 0; p < 4; p++) {
                uint32_t b0, b1, b2, b3;
                LDSM_X4(b0, b1, b2, b3, kaddr + p * (16 * 68 * 4) + ks * 32);
                mma_tf32(sacc[2 * p],     qf[ks][0], qf[ks][1], qf[ks][2], qf[ks][3], b0, b1);
                mma_tf32(sacc[2 * p + 1], qf[ks][0], qf[ks][1], qf[ks][2], qf[ks][3], b2, b3);
            }
        }

        // ---- online softmax ----
        float mx0 = -1e30f, mx1 = -1e30f;
#pragma unroll
        for (int nt = 0; nt < 8; nt++) {
            mx0 = fmaxf(mx0, fmaxf(sacc[nt][0], sacc[nt][1]));
            mx1 = fmaxf(mx1, fmaxf(sacc[nt][2], sacc[nt][3]));
        }
        mx0 = fmaxf(mx0, __shfl_xor_sync(0xffffffffu, mx0, 1));
        mx0 = fmaxf(mx0, __shfl_xor_sync(0xffffffffu, mx0, 2));
        mx1 = fmaxf(mx1, __shfl_xor_sync(0xffffffffu, mx1, 1));
        mx1 = fmaxf(mx1, __shfl_xor_sync(0xffffffffu, mx1, 2));
        float mn0 = fmaxf(mrow0, mx0), mn1 = fmaxf(mrow1, mx1);
        float corr0 = __expf(mrow0 - mn0), corr1 = __expf(mrow1 - mn1);
        float ps0 = 0.0f, ps1 = 0.0f;
#pragma unroll
        for (int nt = 0; nt < 8; nt++) {
            sacc[nt][0] = __expf(sacc[nt][0] - mn0);
            sacc[nt][1] = __expf(sacc[nt][1] - mn0);
            sacc[nt][2] = __expf(sacc[nt][2] - mn1);
            sacc[nt][3] = __expf(sacc[nt][3] - mn1);
            ps0 += sacc[nt][0] + sacc[nt][1];
            ps1 += sacc[nt][2] + sacc[nt][3];
        }
        ps0 += __shfl_xor_sync(0xffffffffu, ps0, 1);
        ps0 += __shfl_xor_sync(0xffffffffu, ps0, 2);
        ps1 += __shfl_xor_sync(0xffffffffu, ps1, 1);
        ps1 += __shfl_xor_sync(0xffffffffu, ps1, 2);
        lrow0 = lrow0 * corr0 + ps0;
        lrow1 = lrow1 * corr1 + ps1;
        mrow0 = mn0; mrow1 = mn1;
#pragma unroll
        for (int dt = 0; dt < 8; dt++) {
            oacc[dt][0] *= corr0; oacc[dt][1] *= corr0;
            oacc[dt][2] *= corr1; oacc[dt][3] *= corr1;
        }

        // ---- P -> per-warp SMEM ----
#pragma unroll
        for (int nt = 0; nt < 8; nt++) {
            *(float2*)&Pw[gid       * 68 + nt * 8 + 2 * tq] =
                make_float2(sacc[nt][0], sacc[nt][1]);
            *(float2*)&Pw[(gid + 8) * 68 + nt * 8 + 2 * tq] =
                make_float2(sacc[nt][2], sacc[nt][3]);
        }
        __syncwarp();

        // ---- O += P @ V ----
#pragma unroll
        for (int ks = 0; ks < 8; ks++) {
            uint32_t pa0, pa1, pa2, pa3;
            LDSM_X4(pa0, pa1, pa2, pa3, paddr + ks * 32);
#pragma unroll
            for (int pd = 0; pd < 4; pd++) {
                uint32_t b0, b1, b2, b3;
                LDSM_X4(b0, b1, b2, b3, vaddr + pd * (16 * 68 * 4) + ks * 32);
                mma_tf32(oacc[2 * pd],     pa0, pa1, pa2, pa3, b0, b1);
                mma_tf32(oacc[2 * pd + 1], pa0, pa1, pa2, pa3, b2, b3);
            }
        }
        __syncwarp();
    }

    // ---- normalize, round to tf32, write ----
    float inv0 = 1.0f / lrow0, inv1 = 1.0f / lrow1;
    float* ob = o + ((size_t)b * Sv + qt * 128 + wid * 16) * Dv + h * HDv;
#pragma unroll
    for (int dt = 0; dt < 8; dt++) {
        int col = dt * 8 + 2 * tq;
        *(float2*)(ob + (size_t)gid * Dv + col) =
            make_float2(rna(oacc[dt][0] * inv0), rna(oacc[dt][1] * inv0));
        *(float2*)(ob + (size_t)(gid + 8) * Dv + col) =
            make_float2(rna(oacc[dt][2] * inv1), rna(oacc[dt][3] * inv1));
    }
}

// ---------------------------------------------------------------------------
// Launch
// ---------------------------------------------------------------------------
extern "C" void kernel_launch(void* const* d_in, const int* in_sizes, int n_in,
                              void* d_out, int out_size)
{
    const float* x  = (const float*)d_in[0];
    const float* Wq = (const float*)d_in[1];
    const float* Wk = (const float*)d_in[2];
    const float* Wv = (const float*)d_in[3];
    const float* Wo = (const float*)d_in[4];
    const float* W1 = (const float*)d_in[5];
    const float* b1 = (const float*)d_in[6];
    const float* W2 = (const float*)d_in[7];
    const float* b2 = (const float*)d_in[8];
    float* out = (float*)d_out;

    float *qk, *vt, *o, *x1, *hbuf, *xr, *wqkvT, *woT, *w1T, *w2T;
    cudaGetSymbolAddress((void**)&qk,    g_qk);
    cudaGetSymbolAddress((void**)&vt,    g_vt);
    cudaGetSymbolAddress((void**)&o,     g_o);
    cudaGetSymbolAddress((void**)&x1,    g_x1);
    cudaGetSymbolAddress((void**)&hbuf,  g_h);
    cudaGetSymbolAddress((void**)&xr,    g_xr);
    cudaGetSymbolAddress((void**)&wqkvT, g_wqkvT);
    cudaGetSymbolAddress((void**)&woT,   g_woT);
    cudaGetSymbolAddress((void**)&w1T,   g_w1T);
    cudaGetSymbolAddress((void**)&w2T,   g_w2T);

    cudaFuncSetAttribute(gemm_mma<EP_QKV, 1>,       cudaFuncAttributeMaxDynamicSharedMemorySize, GEMM_SMEM);
    cudaFuncSetAttribute(gemm_mma<EP_RES, 1>,       cudaFuncAttributeMaxDynamicSharedMemorySize, GEMM_SMEM);
    cudaFuncSetAttribute(gemm_mma<EP_BIAS_GELU, 1>, cudaFuncAttributeMaxDynamicSharedMemorySize, GEMM_SMEM);
    cudaFuncSetAttribute(gemm_mma<EP_BIAS_RES, 0>,  cudaFuncAttributeMaxDynamicSharedMemorySize, GEMM_SMEM);
    cudaFuncSetAttribute(attn_mma, cudaFuncAttributeMaxDynamicSharedMemorySize, ATTN_SMEM);

    const float scale = 0.21022410381342865f;  // 512^(-0.25)
    dim3 blk(256);
    dim3 tblk(32, 8);

    // Pre-transpose + round weights; round x.
    transpose_rnd<<<dim3(16, 16), tblk>>>(Wq, wqkvT,             Dv, Dv, scale);
    transpose_rnd<<<dim3(16, 16), tblk>>>(Wk, wqkvT + 512 * Dv,  Dv, Dv, scale);
    transpose_rnd<<<dim3(16, 16), tblk>>>(Wv, wqkvT + 1024 * Dv, Dv, Dv, 1.0f);
    transpose_rnd<<<dim3(16, 16), tblk>>>(Wo, woT,               Dv, Dv, 1.0f);
    transpose_rnd<<<dim3(64, 16), tblk>>>(W1, w1T,  Dv, DEv, 1.0f);
    transpose_rnd<<<dim3(16, 64), tblk>>>(W2, w2T,  DEv, Dv, 1.0f);
    round_x<<<256, blk>>>(x);

    // qkv projections: q|k -> g_qk, v -> g_vt (transposed), all rounded
    gemm_mma<EP_QKV, 1><<<dim3(QKVN / 128, Mv / 128), blk, GEMM_SMEM>>>(
        xr, wqkvT, nullptr, vt, qk, Mv, QKVN, Dv);

    attn_mma<<<dim3(Sv / 128, Hv, Bv), blk, ATTN_SMEM>>>(qk, vt, o);

    // x1 = o @ Wo + x (rounded for next GEMM's A)
    gemm_mma<EP_RES, 1><<<dim3(Dv / 128, Mv / 128), blk, GEMM_SMEM>>>(
        o, woT, nullptr, x, x1, Mv, Dv, Dv);
    // h = gelu(x1 @ W1 + b1) (rounded)
    gemm_mma<EP_BIAS_GELU, 1><<<dim3(DEv / 128, Mv / 128), blk, GEMM_SMEM>>>(
        x1, w1T, b1, nullptr, hbuf, Mv, DEv, Dv);
    // out = h @ W2 + b2 + x1
    gemm_mma<EP_BIAS_RES, 0><<<dim3(Dv / 128, Mv / 128), blk, GEMM_SMEM>>>(
        hbuf, w2T, b2, x1, out, Mv, Dv, DEv);
}